// round 1
// baseline (speedup 1.0000x reference)
#include <cuda_runtime.h>

// VectorQuantize: H=1, N=32768 tokens, D=256, K=4096 codes.
// argmin_k ||x - e_k||  ==  argmin_k (e2[k] - 2*x.e_k), then gather e[best].
// Round 1: exact fp32 FFMA register-tiled kernel with fused argmin.

#define N_TOK 32768
#define DIM   256
#define KCODE 4096

#define BM 128   // tokens per block
#define BK 128   // codes per k-tile
#define DK 32    // D chunk staged in smem
#define TM 8
#define TN 8
#define NTHREADS 256

__device__ float g_e2[KCODE];
__device__ int   g_idx[N_TOK];

// ---------------------------------------------------------------------------
// Kernel 0: e2[k] = sum_d embed[k][d]^2  (one warp per codebook row)
// ---------------------------------------------------------------------------
__global__ void e2_kernel(const float* __restrict__ embed) {
    int warp = (blockIdx.x * blockDim.x + threadIdx.x) >> 5;
    int lane = threadIdx.x & 31;
    if (warp >= KCODE) return;
    const float* row = embed + (size_t)warp * DIM;
    float s = 0.f;
#pragma unroll
    for (int i = 0; i < DIM / 32; i++) {
        float v = row[lane + 32 * i];
        s = fmaf(v, v, s);
    }
#pragma unroll
    for (int o = 16; o > 0; o >>= 1) s += __shfl_xor_sync(0xffffffffu, s, o);
    if (lane == 0) g_e2[warp] = s;
}

// ---------------------------------------------------------------------------
// Kernel 1: fused GEMM + argmin.
// Block = 128 tokens. Loop over 32 k-tiles of 128 codes; per k-tile accumulate
// xe over D in DK=32 chunks through smem, then fold into running (bestv,bestk).
// ---------------------------------------------------------------------------
__global__ __launch_bounds__(NTHREADS)
void assign_kernel(const float* __restrict__ x, const float* __restrict__ embed) {
    __shared__ __align__(16) union {
        struct {
            float xs[BM][DK];       // x tile, row-major (conflict-free f4 ld/st)
            float es[DK][BK + 4];   // embed tile, transposed (+4 pad)
        } tiles;
        struct {
            float sv[16][BM];       // per-column-group partial min values
            int   si[16][BM];       // per-column-group partial min indices
        } red;
    } sm;

    const int t  = threadIdx.x;
    const int tx = t & 15;          // column group
    const int ty = t >> 4;          // row group
    const int rowbase = ty * TM;
    const int colbase = tx * TN;
    const int n0 = blockIdx.x * BM;

    float bestv[TM];
    int   bestk[TM];
#pragma unroll
    for (int r = 0; r < TM; r++) { bestv[r] = 3.4e38f; bestk[r] = 0; }

    for (int k0 = 0; k0 < KCODE; k0 += BK) {
        float acc[TM][TN];
#pragma unroll
        for (int r = 0; r < TM; r++)
#pragma unroll
            for (int c = 0; c < TN; c++) acc[r][c] = 0.f;

        for (int dc = 0; dc < DIM; dc += DK) {
            __syncthreads();   // previous stage's smem reads complete
            // Stage tiles: 128 rows x 32 cols each (1024 float4s / tile).
#pragma unroll
            for (int j = 0; j < 4; j++) {
                int idx = t + NTHREADS * j;     // 0..1023
                int row = idx >> 3;             // 0..127
                int f   = idx & 7;              // float4 slot within the 32 cols
                float4 v = *(const float4*)(x + (size_t)(n0 + row) * DIM + dc + f * 4);
                sm.tiles.xs[row][f * 4 + 0] = v.x;
                sm.tiles.xs[row][f * 4 + 1] = v.y;
                sm.tiles.xs[row][f * 4 + 2] = v.z;
                sm.tiles.xs[row][f * 4 + 3] = v.w;
                float4 w = *(const float4*)(embed + (size_t)(k0 + row) * DIM + dc + f * 4);
                sm.tiles.es[f * 4 + 0][row] = w.x;
                sm.tiles.es[f * 4 + 1][row] = w.y;
                sm.tiles.es[f * 4 + 2][row] = w.z;
                sm.tiles.es[f * 4 + 3][row] = w.w;
            }
            __syncthreads();

#pragma unroll
            for (int d = 0; d < DK; d++) {
                float b[TN];
                *(float4*)&b[0] = *(const float4*)&sm.tiles.es[d][colbase];
                *(float4*)&b[4] = *(const float4*)&sm.tiles.es[d][colbase + 4];
                float a[TM];
#pragma unroll
                for (int r = 0; r < TM; r++) a[r] = sm.tiles.xs[rowbase + r][d];
#pragma unroll
                for (int r = 0; r < TM; r++)
#pragma unroll
                    for (int c = 0; c < TN; c++)
                        acc[r][c] = fmaf(a[r], b[c], acc[r][c]);
            }
        }

        // Fold this k-tile into the running argmin.
        // c ascending + strict '<' keeps the smallest index on ties.
#pragma unroll
        for (int c = 0; c < TN; c++) {
            int   k  = k0 + colbase + c;
            float e2 = __ldg(&g_e2[k]);
#pragma unroll
            for (int r = 0; r < TM; r++) {
                float s = fmaf(-2.f, acc[r][c], e2);
                if (s < bestv[r]) { bestv[r] = s; bestk[r] = k; }
            }
        }
    }

    // Cross-thread reduction (16 column groups per token row).
    __syncthreads();   // done reading tiles; smem union repurposed
#pragma unroll
    for (int r = 0; r < TM; r++) {
        sm.red.sv[tx][rowbase + r] = bestv[r];
        sm.red.si[tx][rowbase + r] = bestk[r];
    }
    __syncthreads();
    if (t < BM) {
        float bv = sm.red.sv[0][t];
        int   bk = sm.red.si[0][t];
#pragma unroll
        for (int g = 1; g < 16; g++) {
            float v = sm.red.sv[g][t];
            int   k = sm.red.si[g][t];
            if (v < bv || (v == bv && k < bk)) { bv = v; bk = k; }
        }
        g_idx[n0 + t] = bk;
    }
}

// ---------------------------------------------------------------------------
// Kernel 2: out[n][:] = embed[g_idx[n]][:]   (4 tokens / 256-thread block)
// ---------------------------------------------------------------------------
__global__ void gather_kernel(const float* __restrict__ embed, float* __restrict__ out) {
    int tok  = blockIdx.x * 4 + (threadIdx.x >> 6);
    int lane = threadIdx.x & 63;
    int k = g_idx[tok];
    float4 v = *(const float4*)(embed + (size_t)k * DIM + lane * 4);
    *(float4*)(out + (size_t)tok * DIM + lane * 4) = v;
}

// ---------------------------------------------------------------------------
extern "C" void kernel_launch(void* const* d_in, const int* in_sizes, int n_in,
                              void* d_out, int out_size) {
    const float* x     = (const float*)d_in[0];
    const float* embed = (const float*)d_in[1];
    // x has N*D=8388608 elems, embed K*D=1048576: swap defensively if reversed.
    if (n_in >= 2 && in_sizes[0] < in_sizes[1]) {
        const float* tmp = x; x = embed; embed = tmp;
    }
    float* out = (float*)d_out;

    e2_kernel<<<KCODE / 8, 256>>>(embed);                 // 4096 warps
    assign_kernel<<<N_TOK / BM, NTHREADS>>>(x, embed);    // 256 blocks
    gather_kernel<<<N_TOK / 4, 256>>>(embed, out);        // 8192 blocks
}

// round 3
// speedup vs baseline: 2.6913x; 2.6913x over previous
#include <cuda_runtime.h>
#include <cstdint>

// VectorQuantize: H=1, N=32768, D=256, K=4096.
// Round 3: tf32 mma.sync screen (top-2/subset candidates) + exact fp32 rescore.
// (tcgen05 unavailable: harness compiles at compute_103, not compute_103a.)

#define N_TOK 32768
#define DIM   256
#define KCODE 4096

#define BM 128                 // tokens per CTA
#define BN 128                 // codes per k-tile
#define DK 32                  // D per stage
#define NKT (KCODE / BN)       // 32
#define NDS (DIM / DK)         // 8
#define NSTAGE (NKT * NDS)     // 256

__device__ float  g_e2[KCODE];
__device__ float2 g_cand[N_TOK][32];   // 16 slots x top-2 (val, idx-as-bits)

// ---------------------------------------------------------------------------
__device__ __forceinline__ void mma_tf32(float d[4], float a0, float a1, float a2, float a3,
                                         float b0, float b1) {
    asm volatile(
        "mma.sync.aligned.m16n8k8.row.col.f32.tf32.tf32.f32 "
        "{%0,%1,%2,%3}, {%4,%5,%6,%7}, {%8,%9}, {%0,%1,%2,%3};"
        : "+f"(d[0]), "+f"(d[1]), "+f"(d[2]), "+f"(d[3])
        : "r"(__float_as_uint(a0)), "r"(__float_as_uint(a1)),
          "r"(__float_as_uint(a2)), "r"(__float_as_uint(a3)),
          "r"(__float_as_uint(b0)), "r"(__float_as_uint(b1)));
}

// ---------------------------------------------------------------------------
__global__ void e2_kernel(const float* __restrict__ embed) {
    int warp = (blockIdx.x * blockDim.x + threadIdx.x) >> 5;
    int lane = threadIdx.x & 31;
    if (warp >= KCODE) return;
    const float* row = embed + (size_t)warp * DIM;
    float s = 0.f;
#pragma unroll
    for (int i = 0; i < DIM / 32; i++) { float v = row[lane + 32 * i]; s = fmaf(v, v, s); }
#pragma unroll
    for (int o = 16; o > 0; o >>= 1) s += __shfl_xor_sync(0xffffffffu, s, o);
    if (lane == 0) g_e2[warp] = s;
}

// ---------------------------------------------------------------------------
// Screen: 256 threads = 8 warps = 2 M-groups x 4 N-groups.
// Warp (wm,wn): rows [wm*64, wm*64+64) (4 m16-tiles), 32 codes of each k-tile
// (4 n8-tiles). smem holds fragments pre-permuted per lane with XOR swizzle:
//   A: [mtile(8)][chunk(4)][comp(4)][32]   comp = jrow + 2*jcol
//   B: [ntile(16)][chunk(4)][comp(2)][32]
//   phys lane index = (gid*4+tig) ^ ((jcol<<4) | chunk)   (injective per warp)
// ---------------------------------------------------------------------------
__global__ __launch_bounds__(256, 1)
void screen_kernel(const float* __restrict__ x, const float* __restrict__ embed) {
    extern __shared__ float sm[];          // 2 bufs x (A 4096 + B 4096) floats
    const int t = threadIdx.x, lane = t & 31, w = t >> 5;
    const int wm = w & 1, wn = w >> 1;
    const int gid = lane >> 2, tig = lane & 3;
    const int n0 = blockIdx.x * BM;

    // staging coords: idx = t + 256*i -> row = (t>>3) + 32*i, f = t&7
    const int f = t & 7, srow = t >> 3;
    const int chs = f >> 1, jcs = f & 1;   // chunk, jcol of this thread's float4s

    float4 pa[4], pb[4];
    float acc[4][4][4];
    float t2v[8][2]; int t2i[8][2];
#pragma unroll
    for (int r = 0; r < 8; r++) { t2v[r][0] = t2v[r][1] = 3.4e38f; t2i[r][0] = t2i[r][1] = 0; }

#define LDG_STAGE(KT, DS)                                                          \
    {                                                                              \
        _Pragma("unroll")                                                          \
        for (int i = 0; i < 4; i++) {                                              \
            int row = srow + 32 * i;                                               \
            pa[i] = *(const float4*)(x + (size_t)(n0 + row) * DIM + (DS) * DK + f * 4);      \
            pb[i] = *(const float4*)(embed + (size_t)((KT) * BN + row) * DIM + (DS) * DK + f * 4); \
        }                                                                          \
    }

#define STS_STAGE(P)                                                               \
    {                                                                              \
        float* wA = sm + (P) * 8192;                                               \
        float* wB = wA + 4096;                                                     \
        _Pragma("unroll")                                                          \
        for (int i = 0; i < 4; i++) {                                              \
            int row = srow + 32 * i;                                               \
            { /* A */                                                              \
                int mt = row >> 4, g = row & 7, jr = (row >> 3) & 1;               \
                float* dst = wA + ((mt * 4 + chs) * 4 + (jr + 2 * jcs)) * 32       \
                                + ((g << 2) ^ (jcs << 4));                         \
                dst[0 ^ chs] = pa[i].x; dst[1 ^ chs] = pa[i].y;                    \
                dst[2 ^ chs] = pa[i].z; dst[3 ^ chs] = pa[i].w;                    \
            }                                                                      \
            { /* B */                                                              \
                int nt = row >> 3, g = row & 7;                                    \
                float* dst = wB + ((nt * 4 + chs) * 2 + jcs) * 32                  \
                                + ((g << 2) ^ (jcs << 4));                         \
                dst[0 ^ chs] = pb[i].x; dst[1 ^ chs] = pb[i].y;                    \
                dst[2 ^ chs] = pb[i].z; dst[3 ^ chs] = pb[i].w;                    \
            }                                                                      \
        }                                                                          \
    }

#define FOLD(R, SV, KI)                                                            \
    {                                                                              \
        float _s = (SV); int _k = (KI);                                            \
        if (_s < t2v[R][0]) { t2v[R][1] = t2v[R][0]; t2i[R][1] = t2i[R][0];        \
                              t2v[R][0] = _s;        t2i[R][0] = _k; }             \
        else if (_s < t2v[R][1]) { t2v[R][1] = _s; t2i[R][1] = _k; }               \
    }

    LDG_STAGE(0, 0);
    STS_STAGE(0);
    __syncthreads();

    for (int s = 0; s < NSTAGE; s++) {
        const int kt = s >> 3, ds = s & 7, p = s & 1;
        if (ds == 0) {
#pragma unroll
            for (int m = 0; m < 4; m++)
#pragma unroll
                for (int n = 0; n < 4; n++)
#pragma unroll
                    for (int q = 0; q < 4; q++) acc[m][n][q] = 0.f;
        }
        if (s + 1 < NSTAGE) LDG_STAGE((s + 1) >> 3, (s + 1) & 7);

        const float* bA = sm + p * 8192;
        const float* bB = bA + 4096;
#pragma unroll
        for (int c = 0; c < 4; c++) {
            float a[4][4];
#pragma unroll
            for (int m = 0; m < 4; m++) {
                const int mt = wm * 4 + m;
                const float* base = bA + (mt * 4 + c) * 4 * 32;
                a[m][0] = base[0 * 32 + (lane ^ c)];
                a[m][1] = base[1 * 32 + (lane ^ c)];
                a[m][2] = base[2 * 32 + (lane ^ (16 | c))];
                a[m][3] = base[3 * 32 + (lane ^ (16 | c))];
            }
            float b[4][2];
#pragma unroll
            for (int n = 0; n < 4; n++) {
                const int nt = wn * 4 + n;
                const float* base = bB + (nt * 4 + c) * 2 * 32;
                b[n][0] = base[0 * 32 + (lane ^ c)];
                b[n][1] = base[1 * 32 + (lane ^ (16 | c))];
            }
#pragma unroll
            for (int m = 0; m < 4; m++)
#pragma unroll
                for (int n = 0; n < 4; n++)
                    mma_tf32(acc[m][n], a[m][0], a[m][1], a[m][2], a[m][3], b[n][0], b[n][1]);
        }
        __syncthreads();
        if (s + 1 < NSTAGE) STS_STAGE((s + 1) & 1);
        __syncthreads();

        if (ds == NDS - 1) {
#pragma unroll
            for (int m = 0; m < 4; m++)
#pragma unroll
                for (int n = 0; n < 4; n++) {
                    const int kc = kt * BN + (wn * 4 + n) * 8 + tig * 2;
                    const float e20 = __ldg(&g_e2[kc]);
                    const float e21 = __ldg(&g_e2[kc + 1]);
                    FOLD(m * 2,     fmaf(-2.f, acc[m][n][0], e20), kc);
                    FOLD(m * 2,     fmaf(-2.f, acc[m][n][1], e21), kc + 1);
                    FOLD(m * 2 + 1, fmaf(-2.f, acc[m][n][2], e20), kc);
                    FOLD(m * 2 + 1, fmaf(-2.f, acc[m][n][3], e21), kc + 1);
                }
        }
    }

    // write per-(lane,row) top-2 candidates
#pragma unroll
    for (int m = 0; m < 4; m++)
#pragma unroll
        for (int j = 0; j < 2; j++) {
            const int r = m * 2 + j;
            const int grow = n0 + wm * 64 + m * 16 + j * 8 + gid;
            const int slot = wn * 4 + tig;
            g_cand[grow][slot * 2 + 0] = make_float2(t2v[r][0], __int_as_float(t2i[r][0]));
            g_cand[grow][slot * 2 + 1] = make_float2(t2v[r][1], __int_as_float(t2i[r][1]));
        }
#undef LDG_STAGE
#undef STS_STAGE
#undef FOLD
}

// ---------------------------------------------------------------------------
// Rescore: 1 warp per token. Merge 32 candidates -> top-4, exact fp32 scores,
// smallest-index tie-break, then gather the winning codeword to out.
// ---------------------------------------------------------------------------
__global__ __launch_bounds__(256)
void rescore_kernel(const float* __restrict__ x, const float* __restrict__ embed,
                    float* __restrict__ out) {
    const int tok  = (blockIdx.x * blockDim.x + threadIdx.x) >> 5;
    const int lane = threadIdx.x & 31;
    if (tok >= N_TOK) return;

    float2 c = g_cand[tok][lane];
    float v = c.x; int ci = __float_as_int(c.y);

    int sel[4];
#pragma unroll
    for (int r = 0; r < 4; r++) {
        float mv = v; int mi = ci;
#pragma unroll
        for (int o = 16; o > 0; o >>= 1) {
            float ov = __shfl_xor_sync(0xffffffffu, mv, o);
            int   oi = __shfl_xor_sync(0xffffffffu, mi, o);
            if (ov < mv || (ov == mv && oi < mi)) { mv = ov; mi = oi; }
        }
        sel[r] = mi;
        if (ci == mi) v = 3.4e38f;
    }

    float xv[8];
#pragma unroll
    for (int q = 0; q < 8; q++) xv[q] = x[(size_t)tok * DIM + lane + 32 * q];

    float bv = 3.4e38f; int bk = 0;
#pragma unroll
    for (int r = 0; r < 4; r++) {
        const int k = sel[r];
        const float* e = embed + (size_t)k * DIM;
        float d = 0.f;
#pragma unroll
        for (int q = 0; q < 8; q++) d = fmaf(xv[q], e[lane + 32 * q], d);
#pragma unroll
        for (int o = 16; o > 0; o >>= 1) d += __shfl_xor_sync(0xffffffffu, d, o);
        float sc = fmaf(-2.f, d, g_e2[k]);
        if (sc < bv || (sc == bv && k < bk)) { bv = sc; bk = k; }
    }

    const float* e = embed + (size_t)bk * DIM;
#pragma unroll
    for (int q = 0; q < 8; q++) out[(size_t)tok * DIM + lane + 32 * q] = e[lane + 32 * q];
}

// ---------------------------------------------------------------------------
extern "C" void kernel_launch(void* const* d_in, const int* in_sizes, int n_in,
                              void* d_out, int out_size) {
    const float* x     = (const float*)d_in[0];
    const float* embed = (const float*)d_in[1];
    if (n_in >= 2 && in_sizes[0] < in_sizes[1]) {
        const float* tmp = x; x = embed; embed = tmp;
    }
    float* out = (float*)d_out;

    cudaFuncSetAttribute(screen_kernel, cudaFuncAttributeMaxDynamicSharedMemorySize, 64 * 1024);

    e2_kernel<<<KCODE / 8, 256>>>(embed);
    screen_kernel<<<N_TOK / BM, 256, 64 * 1024>>>(x, embed);
    rescore_kernel<<<N_TOK / 8, 256>>>(x, embed, out);
}

// round 4
// speedup vs baseline: 3.2206x; 1.1966x over previous
#include <cuda_runtime.h>
#include <cstdint>

// VectorQuantize: H=1, N=32768, D=256, K=4096.
// Round 4: int8 IMMA screen (exact int32 scores of quantized metric),
//          resident-A barrier-free mainloop, top-16 exact fp32 rescore.

#define N_TOK 32768
#define DIM   256
#define KCODE 4096
#define BM    128
#define NKT   (KCODE / 128)     // 32 k-tiles of 128 codes

__device__ float    g_e2[KCODE];             // exact fp32 sum e^2 (rescore)
__device__ int      g_e2s[KCODE];            // int sum of q_e^2 (screen)
__device__ uint32_t g_e8[512 * 8 * 32 * 2];  // B fragments: [nt][c][lane][hk]
__device__ int2     g_cand[N_TOK][64];       // (int score, col) candidates

// ---------------------------------------------------------------------------
__device__ __forceinline__ void imma16832(int c[4], uint32_t a0, uint32_t a1,
                                          uint32_t a2, uint32_t a3,
                                          uint32_t b0, uint32_t b1) {
    asm volatile(
        "mma.sync.aligned.m16n8k32.row.col.s32.s8.s8.s32 "
        "{%0,%1,%2,%3}, {%4,%5,%6,%7}, {%8,%9}, {%0,%1,%2,%3};"
        : "+r"(c[0]), "+r"(c[1]), "+r"(c[2]), "+r"(c[3])
        : "r"(a0), "r"(a1), "r"(a2), "r"(a3), "r"(b0), "r"(b1));
}

__device__ __forceinline__ int q8(float v) {
    int q = __float2int_rn(v * 32.0f);
    return max(-127, min(127, q));
}
__device__ __forceinline__ uint32_t pack4(int q0, int q1, int q2, int q3) {
    return (uint32_t)(q0 & 0xFF) | ((uint32_t)(q1 & 0xFF) << 8) |
           ((uint32_t)(q2 & 0xFF) << 16) | ((uint32_t)(q3 & 0xFF) << 24);
}

// ---------------------------------------------------------------------------
// equant: embed -> int8 B-fragment layout + int e2s + exact fp32 e2.
// One warp per code row; lane owns dims [lane*8, lane*8+8).
// ---------------------------------------------------------------------------
__global__ void equant_kernel(const float* __restrict__ embed) {
    const int n    = (blockIdx.x * blockDim.x + threadIdx.x) >> 5;
    const int lane = threadIdx.x & 31;
    if (n >= KCODE) return;
    const float* row = embed + (size_t)n * DIM;

    float4 va = *(const float4*)(row + lane * 8);
    float4 vb = *(const float4*)(row + lane * 8 + 4);

    int   qa[8] = {q8(va.x), q8(va.y), q8(va.z), q8(va.w),
                   q8(vb.x), q8(vb.y), q8(vb.z), q8(vb.w)};
    float fv[8] = {va.x, va.y, va.z, va.w, vb.x, vb.y, vb.z, vb.w};

    int   s2i = 0;
    float s2f = 0.f;
#pragma unroll
    for (int i = 0; i < 8; i++) { s2i += qa[i] * qa[i]; s2f = fmaf(fv[i], fv[i], s2f); }
#pragma unroll
    for (int o = 16; o > 0; o >>= 1) {
        s2i += __shfl_xor_sync(0xffffffffu, s2i, o);
        s2f += __shfl_xor_sync(0xffffffffu, s2f, o);
    }
    if (lane == 0) { g_e2s[n] = s2i; g_e2[n] = s2f; }

    const int nt = n >> 3, gidn = n & 7;
#pragma unroll
    for (int u = 0; u < 2; u++) {
        int k0 = lane * 8 + 4 * u;
        int c = k0 >> 5, hk = (k0 >> 4) & 1, tg = (k0 >> 2) & 3;
        uint32_t w = pack4(qa[4 * u], qa[4 * u + 1], qa[4 * u + 2], qa[4 * u + 3]);
        g_e8[(((nt * 8 + c) * 32 + gidn * 4 + tg) << 1) + hk] = w;
    }
}

// ---------------------------------------------------------------------------
// Screen: 512 threads = 16 warps = 2 wm (64 rows) x 8 wn (2 ntiles/ktile).
// A (x, int8 fragments) resident in smem; B fragments LDG'd from g_e8 (L2).
// Zero __syncthreads in the mainloop. Exact int32 argmin of quantized d^2,
// top-2 per (lane,row-slot) packed as ((s+2^24)<<7 | loc) unsigned.
// ---------------------------------------------------------------------------
__global__ __launch_bounds__(512, 1)
void screen_kernel(const float* __restrict__ x) {
    __shared__ uint32_t sA[8192];   // [mt(8)][c(8)][lane(32)][r(4)] = 32KB

    const int t = threadIdx.x, lane = t & 31, w = t >> 5;
    const int wm = w & 1, wn = w >> 1;
    const int gid = lane >> 2, tig = lane & 3;
    const int n0 = blockIdx.x * BM;

    // ---- convert x tile to int8 A fragments (one time) ----
#pragma unroll
    for (int i = 0; i < 16; i++) {
        int wid = t + 512 * i;          // 8192 words
        int row = wid >> 6, wk = wid & 63, k0 = wk * 4;
        float4 v = *(const float4*)(x + (size_t)(n0 + row) * DIM + k0);
        uint32_t pw = pack4(q8(v.x), q8(v.y), q8(v.z), q8(v.w));
        int mt = row >> 4, gr = row & 7, jr = (row >> 3) & 1;
        int c = k0 >> 5, hk = (k0 >> 4) & 1, tg = (k0 >> 2) & 3;
        sA[(((mt * 8 + c) * 32 + gr * 4 + tg) << 2) + jr + 2 * hk] = pw;
    }
    __syncthreads();

    uint32_t t2a[8], t2b[8];
#pragma unroll
    for (int s = 0; s < 8; s++) { t2a[s] = 0xFFFFFFFFu; t2b[s] = 0xFFFFFFFFu; }

    for (int kt = 0; kt < NKT; kt++) {
        int acc[4][2][4];
#pragma unroll
        for (int m = 0; m < 4; m++)
#pragma unroll
            for (int nn = 0; nn < 2; nn++)
#pragma unroll
                for (int q = 0; q < 4; q++) acc[m][nn][q] = 0;

        const int ntg0 = kt * 16 + wn * 2;
#pragma unroll
        for (int c = 0; c < 8; c++) {
            uint2 b0 = *(const uint2*)&g_e8[(((ntg0 + 0) * 8 + c) * 32 + lane) << 1];
            uint2 b1 = *(const uint2*)&g_e8[(((ntg0 + 1) * 8 + c) * 32 + lane) << 1];
#pragma unroll
            for (int m = 0; m < 4; m++) {
                const int mt = wm * 4 + m;
                uint4 av = *(const uint4*)&sA[((mt * 8 + c) * 32 + lane) << 2];
                imma16832(acc[m][0], av.x, av.y, av.z, av.w, b0.x, b0.y);
                imma16832(acc[m][1], av.x, av.y, av.z, av.w, b1.x, b1.y);
            }
        }

        // fold: score = e2s[col] - 2*xe  (exact int32)
#pragma unroll
        for (int nn = 0; nn < 2; nn++) {
            const int colb = kt * 128 + (wn * 2 + nn) * 8 + tig * 2;
            const int e20 = __ldg(&g_e2s[colb]);
            const int e21 = __ldg(&g_e2s[colb + 1]);
#pragma unroll
            for (int m = 0; m < 4; m++)
#pragma unroll
                for (int jr = 0; jr < 2; jr++) {
#pragma unroll
                    for (int j = 0; j < 2; j++) {
                        int s = (j ? e21 : e20) - 2 * acc[m][nn][jr * 2 + j];
                        uint32_t p = (uint32_t)((s << 7) |
                                     (kt * 4 + nn * 2 + j)) ^ 0x80000000u;
                        const int sl = m * 2 + jr;
                        if (p < t2a[sl])      { t2b[sl] = t2a[sl]; t2a[sl] = p; }
                        else if (p < t2b[sl]) { t2b[sl] = p; }
                    }
                }
        }
    }

    // ---- emit candidates ----
#pragma unroll
    for (int m = 0; m < 4; m++)
#pragma unroll
        for (int jr = 0; jr < 2; jr++) {
            const int sl  = m * 2 + jr;
            const int row = n0 + wm * 64 + m * 16 + jr * 8 + gid;
            const int sb  = (wn * 4 + tig) * 2;
#pragma unroll
            for (int u = 0; u < 2; u++) {
                uint32_t p = (u ? t2b[sl] : t2a[sl]) ^ 0x80000000u;
                int s   = ((int)p) >> 7;
                int loc = (int)(p & 127);
                int col = (loc >> 2) * 128 + (wn * 2 + ((loc >> 1) & 1)) * 8 +
                          tig * 2 + (loc & 1);
                g_cand[row][sb + u] = make_int2(s, col);
            }
        }
}

// ---------------------------------------------------------------------------
// Rescore: warp per token. Pick top-16 of 64 candidates by (score, col),
// exact fp32 rescoring, smallest-index tie-break, gather winner.
// ---------------------------------------------------------------------------
__global__ __launch_bounds__(256)
void rescore_kernel(const float* __restrict__ x, const float* __restrict__ embed,
                    float* __restrict__ out) {
    const int tok  = (blockIdx.x * blockDim.x + threadIdx.x) >> 5;
    const int lane = threadIdx.x & 31;
    if (tok >= N_TOK) return;

    int2 c0 = g_cand[tok][lane];
    int2 c1 = g_cand[tok][lane + 32];
    long long p0 = ((long long)c0.x << 13) | (long long)c0.y;
    long long p1 = ((long long)c1.x << 13) | (long long)c1.y;
    if (p1 < p0) { long long tmp = p0; p0 = p1; p1 = tmp; }

    int sel[16];
#pragma unroll
    for (int r = 0; r < 16; r++) {
        long long mv = p0;
#pragma unroll
        for (int o = 16; o > 0; o >>= 1) {
            long long ov = __shfl_xor_sync(0xffffffffu, mv, o);
            if (ov < mv) mv = ov;
        }
        sel[r] = (int)(mv & 0x1FFF);
        if (p0 == mv) { p0 = p1; p1 = 0x7FFFFFFFFFFFFFFFLL; }
    }

    float xv[8];
#pragma unroll
    for (int q = 0; q < 8; q++) xv[q] = x[(size_t)tok * DIM + lane + 32 * q];

    float bv = 3.4e38f; int bk = KCODE;
#pragma unroll
    for (int r = 0; r < 16; r++) {
        const int k = sel[r];
        const float* e = embed + (size_t)k * DIM;
        float d = 0.f;
#pragma unroll
        for (int q = 0; q < 8; q++) d = fmaf(xv[q], e[lane + 32 * q], d);
#pragma unroll
        for (int o = 16; o > 0; o >>= 1) d += __shfl_xor_sync(0xffffffffu, d, o);
        float sc = fmaf(-2.f, d, g_e2[k]);
        if (sc < bv || (sc == bv && k < bk)) { bv = sc; bk = k; }
    }

    const float* e = embed + (size_t)bk * DIM;
#pragma unroll
    for (int q = 0; q < 8; q++)
        out[(size_t)tok * DIM + lane + 32 * q] = e[lane + 32 * q];
}

// ---------------------------------------------------------------------------
extern "C" void kernel_launch(void* const* d_in, const int* in_sizes, int n_in,
                              void* d_out, int out_size) {
    const float* x     = (const float*)d_in[0];
    const float* embed = (const float*)d_in[1];
    if (n_in >= 2 && in_sizes[0] < in_sizes[1]) {
        const float* tmp = x; x = embed; embed = tmp;
    }
    float* out = (float*)d_out;

    equant_kernel<<<KCODE / 8, 256>>>(embed);
    screen_kernel<<<N_TOK / BM, 512>>>(x);
    rescore_kernel<<<N_TOK / 8, 256>>>(x, embed, out);
}